// round 2
// baseline (speedup 1.0000x reference)
#include <cuda_runtime.h>
#include <cstdint>
#include <cstddef>

#define TILE 64
#define TK 16

// ---------------- scratch (device globals; no allocations allowed) ----------
__device__ float g_h[2048 * 1024];     // relu(x@M1^T+bm1)
__device__ float g_enh[4096 * 1024];   // [mem ; x]
__device__ float g_Q[4096 * 1024];
__device__ float g_K[4096 * 1024];
__device__ float g_V[4096 * 1024];
__device__ float g_ctx[2048 * 1024];   // only q in [S,2S) per batch

// ---------------- generic NT GEMM: C = act(scale*(A @ B^T) + bias) ----------
// A: M x K (lda), B: N x K (ldb), C: M x N (ldc). M,N multiples of 64, K of 16.
__global__ void __launch_bounds__(256) gemm_nt_kernel(
    const float* __restrict__ A, const float* __restrict__ B,
    const float* __restrict__ bias, float* __restrict__ C,
    int K, int lda, int ldb, int ldc, float scale, int relu)
{
    __shared__ float As[TK][TILE + 4];
    __shared__ float Bs[TK][TILE + 4];
    const int tid = threadIdx.x;
    const int tx = tid & 15, ty = tid >> 4;
    const int m0 = blockIdx.y * TILE;
    const int n0 = blockIdx.x * TILE;
    const int lrow = tid >> 2;
    const int lkv = (tid & 3) << 2;

    float acc[4][4] = {};

    const float* Arow = A + (size_t)(m0 + lrow) * lda + lkv;
    const float* Brow = B + (size_t)(n0 + lrow) * ldb + lkv;

    for (int kt = 0; kt < K; kt += TK) {
        float4 av = *reinterpret_cast<const float4*>(Arow + kt);
        float4 bv = *reinterpret_cast<const float4*>(Brow + kt);
        As[lkv + 0][lrow] = av.x; As[lkv + 1][lrow] = av.y;
        As[lkv + 2][lrow] = av.z; As[lkv + 3][lrow] = av.w;
        Bs[lkv + 0][lrow] = bv.x; Bs[lkv + 1][lrow] = bv.y;
        Bs[lkv + 2][lrow] = bv.z; Bs[lkv + 3][lrow] = bv.w;
        __syncthreads();
#pragma unroll
        for (int k = 0; k < TK; k++) {
            float4 a4 = *reinterpret_cast<const float4*>(&As[k][ty << 2]);
            float4 b4 = *reinterpret_cast<const float4*>(&Bs[k][tx << 2]);
            float a[4] = {a4.x, a4.y, a4.z, a4.w};
            float b[4] = {b4.x, b4.y, b4.z, b4.w};
#pragma unroll
            for (int i = 0; i < 4; i++)
#pragma unroll
                for (int j = 0; j < 4; j++) acc[i][j] += a[i] * b[j];
        }
        __syncthreads();
    }

#pragma unroll
    for (int i = 0; i < 4; i++) {
        int m = m0 + (ty << 2) + i;
#pragma unroll
        for (int j = 0; j < 4; j++) {
            int n = n0 + (tx << 2) + j;
            float v = acc[i][j] * scale;
            if (bias) v += bias[n];
            if (relu) v = fmaxf(v, 0.0f);
            C[(size_t)m * ldc + n] = v;
        }
    }
}

// ---------------- QK^T per (b,h): scores = 0.125 * Q_bh @ K_bh^T ------------
// Q,K: 4096 x 1024 (row = b*2048+q, col = h*64+d). Out: attn[z] 2048x2048.
__global__ void __launch_bounds__(256) qk_kernel(
    const float* __restrict__ Q, const float* __restrict__ Km,
    float* __restrict__ attn)
{
    __shared__ float As[TK][TILE + 4];
    __shared__ float Bs[TK][TILE + 4];
    const int z = blockIdx.z, b = z >> 4, h = z & 15;
    const float* A = Q + (size_t)b * 2048 * 1024 + h * 64;
    const float* B = Km + (size_t)b * 2048 * 1024 + h * 64;
    float* C = attn + (size_t)z * 2048 * 2048;

    const int tid = threadIdx.x;
    const int tx = tid & 15, ty = tid >> 4;
    const int m0 = blockIdx.y * TILE;
    const int n0 = blockIdx.x * TILE;
    const int lrow = tid >> 2;
    const int lkv = (tid & 3) << 2;

    float acc[4][4] = {};

    const float* Arow = A + (size_t)(m0 + lrow) * 1024 + lkv;
    const float* Brow = B + (size_t)(n0 + lrow) * 1024 + lkv;

#pragma unroll
    for (int kt = 0; kt < 64; kt += TK) {
        float4 av = *reinterpret_cast<const float4*>(Arow + kt);
        float4 bv = *reinterpret_cast<const float4*>(Brow + kt);
        As[lkv + 0][lrow] = av.x; As[lkv + 1][lrow] = av.y;
        As[lkv + 2][lrow] = av.z; As[lkv + 3][lrow] = av.w;
        Bs[lkv + 0][lrow] = bv.x; Bs[lkv + 1][lrow] = bv.y;
        Bs[lkv + 2][lrow] = bv.z; Bs[lkv + 3][lrow] = bv.w;
        __syncthreads();
#pragma unroll
        for (int k = 0; k < TK; k++) {
            float4 a4 = *reinterpret_cast<const float4*>(&As[k][ty << 2]);
            float4 b4 = *reinterpret_cast<const float4*>(&Bs[k][tx << 2]);
            float a[4] = {a4.x, a4.y, a4.z, a4.w};
            float b[4] = {b4.x, b4.y, b4.z, b4.w};
#pragma unroll
            for (int i = 0; i < 4; i++)
#pragma unroll
                for (int j = 0; j < 4; j++) acc[i][j] += a[i] * b[j];
        }
        __syncthreads();
    }

#pragma unroll
    for (int i = 0; i < 4; i++) {
        int m = m0 + (ty << 2) + i;
#pragma unroll
        for (int j = 0; j < 4; j++) {
            int n = n0 + (tx << 2) + j;
            C[(size_t)m * 2048 + n] = acc[i][j] * 0.125f;
        }
    }
}

// ---------------- row softmax in-place: 65536 rows x 2048 -------------------
__global__ void __launch_bounds__(256) softmax_kernel(float* __restrict__ attn)
{
    float4* p = reinterpret_cast<float4*>(attn + (size_t)blockIdx.x * 2048);
    const int tid = threadIdx.x;
    float4 v0 = p[tid];
    float4 v1 = p[tid + 256];

    float mx = fmaxf(fmaxf(fmaxf(v0.x, v0.y), fmaxf(v0.z, v0.w)),
                     fmaxf(fmaxf(v1.x, v1.y), fmaxf(v1.z, v1.w)));
#pragma unroll
    for (int o = 16; o; o >>= 1) mx = fmaxf(mx, __shfl_xor_sync(0xffffffffu, mx, o));

    __shared__ float smax[8], ssum[8];
    if ((tid & 31) == 0) smax[tid >> 5] = mx;
    __syncthreads();
    float m = smax[0];
#pragma unroll
    for (int i = 1; i < 8; i++) m = fmaxf(m, smax[i]);

    v0.x = __expf(v0.x - m); v0.y = __expf(v0.y - m);
    v0.z = __expf(v0.z - m); v0.w = __expf(v0.w - m);
    v1.x = __expf(v1.x - m); v1.y = __expf(v1.y - m);
    v1.z = __expf(v1.z - m); v1.w = __expf(v1.w - m);

    float s = v0.x + v0.y + v0.z + v0.w + v1.x + v1.y + v1.z + v1.w;
#pragma unroll
    for (int o = 16; o; o >>= 1) s += __shfl_xor_sync(0xffffffffu, s, o);
    if ((tid & 31) == 0) ssum[tid >> 5] = s;
    __syncthreads();
    float tot = 0.0f;
#pragma unroll
    for (int i = 0; i < 8; i++) tot += ssum[i];
    float inv = 1.0f / tot;

    v0.x *= inv; v0.y *= inv; v0.z *= inv; v0.w *= inv;
    v1.x *= inv; v1.y *= inv; v1.z *= inv; v1.w *= inv;
    p[tid] = v0;
    p[tid + 256] = v1;
}

// ---------------- ctx = attn[:, 1024:, :] @ V_bh (NN, N=64) -----------------
__global__ void __launch_bounds__(256) av_kernel(
    const float* __restrict__ attn, const float* __restrict__ V,
    float* __restrict__ ctx)
{
    __shared__ float As[TK][TILE + 4];
    __shared__ float Bs[TK][TILE + 4];
    const int z = blockIdx.z, b = z >> 4, h = z & 15;
    const float* A = attn + (size_t)z * 2048 * 2048 + (size_t)1024 * 2048;
    const float* Bv = V + (size_t)b * 2048 * 1024 + h * 64;
    float* C = ctx + (size_t)b * 1024 * 1024 + h * 64;

    const int tid = threadIdx.x;
    const int tx = tid & 15, ty = tid >> 4;
    const int m0 = blockIdx.y * TILE;
    const int lrow = tid >> 2;            // A-tile row 0..63
    const int lkv = (tid & 3) << 2;       // A-tile k-offset
    const int brow = tid >> 4;            // B-tile k-row 0..15
    const int bcol = (tid & 15) << 2;     // B-tile n-offset

    float acc[4][4] = {};

    for (int kt = 0; kt < 2048; kt += TK) {
        float4 av = *reinterpret_cast<const float4*>(
            A + (size_t)(m0 + lrow) * 2048 + kt + lkv);
        As[lkv + 0][lrow] = av.x; As[lkv + 1][lrow] = av.y;
        As[lkv + 2][lrow] = av.z; As[lkv + 3][lrow] = av.w;
        *reinterpret_cast<float4*>(&Bs[brow][bcol]) =
            *reinterpret_cast<const float4*>(Bv + (size_t)(kt + brow) * 1024 + bcol);
        __syncthreads();
#pragma unroll
        for (int k = 0; k < TK; k++) {
            float4 a4 = *reinterpret_cast<const float4*>(&As[k][ty << 2]);
            float4 b4 = *reinterpret_cast<const float4*>(&Bs[k][tx << 2]);
            float a[4] = {a4.x, a4.y, a4.z, a4.w};
            float b[4] = {b4.x, b4.y, b4.z, b4.w};
#pragma unroll
            for (int i = 0; i < 4; i++)
#pragma unroll
                for (int j = 0; j < 4; j++) acc[i][j] += a[i] * b[j];
        }
        __syncthreads();
    }

#pragma unroll
    for (int i = 0; i < 4; i++) {
        int m = m0 + (ty << 2) + i;
#pragma unroll
        for (int j = 0; j < 4; j++) {
            int n = (tx << 2) + j;
            C[(size_t)m * 1024 + n] = acc[i][j];
        }
    }
}

// ---------------- launch -----------------------------------------------------
extern "C" void kernel_launch(void* const* d_in, const int* in_sizes, int n_in,
                              void* d_out, int out_size)
{
    const float* x   = (const float*)d_in[0];
    const float* Wq  = (const float*)d_in[1];
    const float* bq  = (const float*)d_in[2];
    const float* Wk  = (const float*)d_in[3];
    const float* bk  = (const float*)d_in[4];
    const float* Wv  = (const float*)d_in[5];
    const float* bv  = (const float*)d_in[6];
    const float* Wo  = (const float*)d_in[7];
    const float* bo  = (const float*)d_in[8];
    const float* M1  = (const float*)d_in[9];
    const float* bm1 = (const float*)d_in[10];
    const float* M2  = (const float*)d_in[11];
    const float* bm2 = (const float*)d_in[12];

    float* out  = (float*)d_out;                       // (2,1024,1024)
    float* attn = out + (size_t)2 * 1024 * 1024;       // (2,16,2048,2048)

    float *ph, *penh, *pQ, *pK, *pV, *pctx;
    cudaGetSymbolAddress((void**)&ph,   g_h);
    cudaGetSymbolAddress((void**)&penh, g_enh);
    cudaGetSymbolAddress((void**)&pQ,   g_Q);
    cudaGetSymbolAddress((void**)&pK,   g_K);
    cudaGetSymbolAddress((void**)&pV,   g_V);
    cudaGetSymbolAddress((void**)&pctx, g_ctx);

    // 1) h = relu(x @ M1^T + bm1)   [2048 x 1024]
    gemm_nt_kernel<<<dim3(16, 32), 256>>>(x, M1, bm1, ph, 1024, 1024, 1024, 1024, 1.0f, 1);
    // 2) enh[0:2048] = h @ M2^T + bm2 ; enh[2048:4096] = x
    gemm_nt_kernel<<<dim3(16, 32), 256>>>(ph, M2, bm2, penh, 1024, 1024, 1024, 1024, 1.0f, 0);
    cudaMemcpyAsync(penh + (size_t)2048 * 1024, x, (size_t)2048 * 1024 * sizeof(float),
                    cudaMemcpyDeviceToDevice, 0);
    // 3) Q,K,V = enh @ W^T + b      [4096 x 1024]
    gemm_nt_kernel<<<dim3(16, 64), 256>>>(penh, Wq, bq, pQ, 1024, 1024, 1024, 1024, 1.0f, 0);
    gemm_nt_kernel<<<dim3(16, 64), 256>>>(penh, Wk, bk, pK, 1024, 1024, 1024, 1024, 1.0f, 0);
    gemm_nt_kernel<<<dim3(16, 64), 256>>>(penh, Wv, bv, pV, 1024, 1024, 1024, 1024, 1.0f, 0);
    // 4) scores = 0.125 * Q_bh @ K_bh^T  -> attn region (pre-softmax)
    qk_kernel<<<dim3(32, 32, 32), 256>>>(pQ, pK, attn);
    // 5) softmax rows in-place (this is the attn output)
    softmax_kernel<<<65536, 256>>>(attn);
    // 6) ctx (only q >= 1024) = attn @ V_bh   [2048 x 1024 packed]
    av_kernel<<<dim3(1, 16, 32), 256>>>(attn, pV, pctx);
    // 7) out_orig = ctx @ Wo^T + bo  [2048 x 1024]
    gemm_nt_kernel<<<dim3(16, 32), 256>>>(pctx, Wo, bo, out, 1024, 1024, 1024, 1024, 1.0f, 0);
}

// round 5
// speedup vs baseline: 2.2963x; 2.2963x over previous
#include <cuda_runtime.h>
#include <cuda_bf16.h>
#include <cstdint>
#include <cstddef>

// ============================================================================
// helpers (base sm_103 ISA only: ldmatrix + mma.sync + cp.async)
// ============================================================================
__device__ __forceinline__ uint32_t smem_u32(const void* p) {
    uint32_t a;
    asm("{ .reg .u64 t; cvta.to.shared.u64 t, %1; cvt.u32.u64 %0, t; }"
        : "=r"(a) : "l"(p));
    return a;
}

#define CP16(dst, src) \
    asm volatile("cp.async.cg.shared.global [%0], [%1], 16;" \
                 :: "r"(dst), "l"(src) : "memory")
#define CP_COMMIT() asm volatile("cp.async.commit_group;" ::: "memory")
#define CP_WAIT1()  asm volatile("cp.async.wait_group 1;" ::: "memory")
#define CP_WAIT0()  asm volatile("cp.async.wait_group 0;" ::: "memory")

#define LDSM4(r, addr) \
    asm volatile("ldmatrix.sync.aligned.m8n8.x4.shared.b16 {%0,%1,%2,%3}, [%4];" \
                 : "=r"((r)[0]), "=r"((r)[1]), "=r"((r)[2]), "=r"((r)[3]) : "r"(addr))

#define MMA16816(d, a, b0, b1) \
    asm volatile("mma.sync.aligned.m16n8k16.row.col.f32.bf16.bf16.f32 " \
                 "{%0,%1,%2,%3},{%4,%5,%6,%7},{%8,%9},{%0,%1,%2,%3};" \
                 : "+f"((d)[0]), "+f"((d)[1]), "+f"((d)[2]), "+f"((d)[3]) \
                 : "r"((a)[0]), "r"((a)[1]), "r"((a)[2]), "r"((a)[3]), \
                   "r"(b0), "r"(b1))

// ============================================================================
// Scratch (device globals; no allocations allowed)
// ============================================================================
__device__ __align__(16) __nv_bfloat16 g_w_hi[6 * 1048576];   // [M1,M2,Wq,Wk,Wv,Wo]
__device__ __align__(16) __nv_bfloat16 g_w_lo[6 * 1048576];
__device__ __align__(16) __nv_bfloat16 g_enh_hi[4194304], g_enh_lo[4194304]; // [mem;x]
__device__ __align__(16) __nv_bfloat16 g_h_hi[2097152],  g_h_lo[2097152];
__device__ __align__(16) __nv_bfloat16 g_q_hi[4194304],  g_q_lo[4194304];
__device__ __align__(16) __nv_bfloat16 g_k_hi[4194304],  g_k_lo[4194304];
__device__ __align__(16) __nv_bfloat16 g_vt_hi[4194304], g_vt_lo[4194304];   // [32][64][2048]
__device__ __align__(16) __nv_bfloat16 g_al_hi[67108864], g_al_lo[67108864]; // attn low half
__device__ __align__(16) __nv_bfloat16 g_ctx_hi[2097152], g_ctx_lo[2097152];

// ============================================================================
// fp32 -> (bf16 hi, bf16 lo)
// ============================================================================
__global__ void __launch_bounds__(256) conv_kernel(
    const float* __restrict__ src, __nv_bfloat16* __restrict__ hi,
    __nv_bfloat16* __restrict__ lo, int n4)
{
    int i = blockIdx.x * 256 + threadIdx.x;
    if (i >= n4) return;
    float4 v = reinterpret_cast<const float4*>(src)[i];
    float vals[4] = {v.x, v.y, v.z, v.w};
    __nv_bfloat16 h[4], l[4];
#pragma unroll
    for (int j = 0; j < 4; ++j) {
        h[j] = __float2bfloat16(vals[j]);
        l[j] = __float2bfloat16(vals[j] - __bfloat162float(h[j]));
    }
    reinterpret_cast<__nv_bfloat162*>(hi)[2 * i]     = {h[0], h[1]};
    reinterpret_cast<__nv_bfloat162*>(hi)[2 * i + 1] = {h[2], h[3]};
    reinterpret_cast<__nv_bfloat162*>(lo)[2 * i]     = {l[0], l[1]};
    reinterpret_cast<__nv_bfloat162*>(lo)[2 * i + 1] = {l[2], l[3]};
}

// ============================================================================
// bf16x3 NT GEMM via mma.sync: C = act(scale*(A@B^T) + bias)
// A: 128-row tiles of M x K (hi/lo), B: BN-row tiles of N x K (hi/lo)
// 3 fused passes per K-chunk: Ahi*Bhi + Alo*Bhi + Ahi*Blo, fp32 reg accum.
// mode 0: plain  mode 1: QK per z=(b,h)  mode 2: AV per z
// transV: scatter C into Vt[32][64][2048]
// ============================================================================
template <int BN>
__global__ void __launch_bounds__(256, 2) gemm3_mma(
    const __nv_bfloat16* __restrict__ Ahi, const __nv_bfloat16* __restrict__ Alo,
    const __nv_bfloat16* __restrict__ Bhi, const __nv_bfloat16* __restrict__ Blo,
    const float* __restrict__ bias,
    float* __restrict__ Cf, __nv_bfloat16* __restrict__ Chi, __nv_bfloat16* __restrict__ Clo,
    int K, int lda, int ldb, int ldc,
    float scale, int relu, int mode, int transV)
{
    extern __shared__ __align__(128) char smem[];
    constexpr int STRIDE = 80;                 // 64B row + 16B pad (16B-aligned)
    constexpr int A_BYTES = 128 * STRIDE;
    constexpr int B_BYTES = BN * STRIDE;
    constexpr int STAGE = 2 * A_BYTES + 2 * B_BYTES;
    constexpr int WM = (BN == 128) ? 2 : 1;

    const int tid = threadIdx.x;
    const int wid = tid >> 5, lid = tid & 31;
    const int m0 = blockIdx.y * 128;
    const int n0 = blockIdx.x * BN;
    const int z  = blockIdx.z;

    const int r0 = (BN == 128) ? ((wid >> 1) * 32) : (wid * 16);
    const int c0 = (BN == 128) ? ((wid & 1) * 64) : 0;

    size_t aOff = 0, bOff = 0;
    if (mode == 1) {
        aOff = bOff = (size_t)(z >> 4) * 2097152 + (size_t)(z & 15) * 64;
    } else if (mode == 2) {
        aOff = (size_t)z * 2097152;
        bOff = (size_t)z * 131072;
    }
    Ahi += aOff; Alo += aOff; Bhi += bOff; Blo += bOff;

    const uint32_t sbase = smem_u32(smem);

    auto issue = [&](int c) {
        const int kt = c << 5;
        const uint32_t sb = sbase + (c & 1) * STAGE;
#pragma unroll
        for (int u = 0; u < 2; ++u) {                  // A hi/lo: 128 rows x 4 segs
            int id = tid + u * 256;
            int row = id >> 2, seg = id & 3;
            const char* sH = (const char*)(Ahi + (size_t)(m0 + row) * lda + kt) + seg * 16;
            const char* sL = (const char*)(Alo + (size_t)(m0 + row) * lda + kt) + seg * 16;
            uint32_t d = sb + row * STRIDE + seg * 16;
            CP16(d, sH);
            CP16(d + A_BYTES, sL);
        }
        constexpr int BU = (BN * 4) / 256;             // B hi/lo
#pragma unroll
        for (int u = 0; u < BU; ++u) {
            int id = tid + u * 256;
            int row = id >> 2, seg = id & 3;
            const char* sH = (const char*)(Bhi + (size_t)(n0 + row) * ldb + kt) + seg * 16;
            const char* sL = (const char*)(Blo + (size_t)(n0 + row) * ldb + kt) + seg * 16;
            uint32_t d = sb + 2 * A_BYTES + row * STRIDE + seg * 16;
            CP16(d, sH);
            CP16(d + B_BYTES, sL);
        }
    };

    float acc[WM][8][4];
#pragma unroll
    for (int i = 0; i < WM; ++i)
#pragma unroll
        for (int j = 0; j < 8; ++j)
#pragma unroll
            for (int q = 0; q < 4; ++q) acc[i][j][q] = 0.0f;

    const int nC = K >> 5;
    issue(0); CP_COMMIT();

    for (int c = 0; c < nC; ++c) {
        if (c + 1 < nC) { issue(c + 1); CP_COMMIT(); CP_WAIT1(); }
        else            { CP_WAIT0(); }
        __syncthreads();

        const uint32_t sb = sbase + (c & 1) * STAGE;
        const uint32_t aH = sb, aL = sb + A_BYTES;
        const uint32_t bH = sb + 2 * A_BYTES, bL = bH + B_BYTES;

        // ldmatrix address components
        const uint32_t aRow = (uint32_t)(r0 + (lid & 15)) * STRIDE + ((lid >> 4) & 1) * 16;
        const uint32_t bRow = (uint32_t)(c0 + (lid & 7) + ((lid >> 4) & 1) * 8) * STRIDE
                            + ((lid >> 3) & 1) * 16;

#pragma unroll
        for (int s = 0; s < 2; ++s) {
            uint32_t ah[WM][4], al[WM][4], bb[4][4];
#pragma unroll
            for (int i = 0; i < WM; ++i) {
                LDSM4(ah[i], aH + aRow + i * 16 * STRIDE + s * 32);
                LDSM4(al[i], aL + aRow + i * 16 * STRIDE + s * 32);
            }
#pragma unroll
            for (int j = 0; j < 4; ++j)
                LDSM4(bb[j], bH + bRow + j * 16 * STRIDE + s * 32);
            // pass 1: Ahi*Bhi ; pass 2: Alo*Bhi
#pragma unroll
            for (int i = 0; i < WM; ++i)
#pragma unroll
                for (int jt = 0; jt < 8; ++jt) {
                    MMA16816(acc[i][jt], ah[i], bb[jt >> 1][(jt & 1) * 2], bb[jt >> 1][(jt & 1) * 2 + 1]);
                    MMA16816(acc[i][jt], al[i], bb[jt >> 1][(jt & 1) * 2], bb[jt >> 1][(jt & 1) * 2 + 1]);
                }
            // pass 3: Ahi*Blo (reuse bb regs)
#pragma unroll
            for (int j = 0; j < 4; ++j)
                LDSM4(bb[j], bL + bRow + j * 16 * STRIDE + s * 32);
#pragma unroll
            for (int i = 0; i < WM; ++i)
#pragma unroll
                for (int jt = 0; jt < 8; ++jt)
                    MMA16816(acc[i][jt], ah[i], bb[jt >> 1][(jt & 1) * 2], bb[jt >> 1][(jt & 1) * 2 + 1]);
        }
        __syncthreads();
    }

    // ---------------- epilogue ----------------
    size_t cOffZ = 0;
    if (mode == 1)      cOffZ = (size_t)z * 4194304;
    else if (mode == 2) cOffZ = (size_t)(z >> 4) * 1048576 + (size_t)(z & 15) * 64;

    const int grp = lid >> 2, tig = lid & 3;

#pragma unroll
    for (int i = 0; i < WM; ++i) {
#pragma unroll
        for (int jt = 0; jt < 8; ++jt) {
            const int mr = m0 + r0 + i * 16 + grp;
            const int nc = n0 + c0 + jt * 8 + tig * 2;
            float v0 = acc[i][jt][0] * scale, v1 = acc[i][jt][1] * scale;
            float v2 = acc[i][jt][2] * scale, v3 = acc[i][jt][3] * scale;
            if (bias) {
                float b0 = __ldg(bias + nc), b1 = __ldg(bias + nc + 1);
                v0 += b0; v1 += b1; v2 += b0; v3 += b1;
            }
            if (relu) {
                v0 = fmaxf(v0, 0.0f); v1 = fmaxf(v1, 0.0f);
                v2 = fmaxf(v2, 0.0f); v3 = fmaxf(v3, 0.0f);
            }
            if (Cf) {
                *reinterpret_cast<float2*>(&Cf[cOffZ + (size_t)mr * ldc + nc]) =
                    make_float2(v0, v1);
                *reinterpret_cast<float2*>(&Cf[cOffZ + (size_t)(mr + 8) * ldc + nc]) =
                    make_float2(v2, v3);
            }
            if (Chi) {
                __nv_bfloat16 h0 = __float2bfloat16(v0), h1 = __float2bfloat16(v1);
                __nv_bfloat16 h2 = __float2bfloat16(v2), h3 = __float2bfloat16(v3);
                __nv_bfloat16 l0 = __float2bfloat16(v0 - __bfloat162float(h0));
                __nv_bfloat16 l1 = __float2bfloat16(v1 - __bfloat162float(h1));
                __nv_bfloat16 l2 = __float2bfloat16(v2 - __bfloat162float(h2));
                __nv_bfloat16 l3 = __float2bfloat16(v3 - __bfloat162float(h3));
                if (!transV) {
                    size_t i0 = cOffZ + (size_t)mr * ldc + nc;
                    size_t i1 = cOffZ + (size_t)(mr + 8) * ldc + nc;
                    *reinterpret_cast<__nv_bfloat162*>(&Chi[i0]) = {h0, h1};
                    *reinterpret_cast<__nv_bfloat162*>(&Chi[i1]) = {h2, h3};
                    *reinterpret_cast<__nv_bfloat162*>(&Clo[i0]) = {l0, l1};
                    *reinterpret_cast<__nv_bfloat162*>(&Clo[i1]) = {l2, l3};
                } else {
                    // Vt[z][d][s]: z=(mr>>11)*16+(nc>>6), d=nc&63, s=mr&2047
#pragma unroll
                    for (int e = 0; e < 4; ++e) {
                        int rr = mr + (e >> 1) * 8;
                        int nn = nc + (e & 1);
                        size_t idx = ((size_t)(rr >> 11) * 16 + (size_t)(nn >> 6)) * 131072
                                   + (size_t)(nn & 63) * 2048 + (size_t)(rr & 2047);
                        __nv_bfloat16 hv = (e == 0) ? h0 : (e == 1) ? h1 : (e == 2) ? h2 : h3;
                        __nv_bfloat16 lv = (e == 0) ? l0 : (e == 1) ? l1 : (e == 2) ? l2 : l3;
                        Chi[idx] = hv;
                        Clo[idx] = lv;
                    }
                }
            }
        }
    }
}

// ============================================================================
// Row softmax in-place (65536 rows x 2048) + bf16 hi/lo export of lower half
// ============================================================================
__global__ void __launch_bounds__(256) softmax_kernel(
    float* __restrict__ attn,
    __nv_bfloat16* __restrict__ lhi, __nv_bfloat16* __restrict__ llo)
{
    const int row = blockIdx.x;
    const int zz = row >> 11;
    const int rr = row & 2047;
    float4* p = reinterpret_cast<float4*>(attn + (size_t)row * 2048);
    const int tid = threadIdx.x;
    float4 v0 = p[tid];
    float4 v1 = p[tid + 256];

    float mx = fmaxf(fmaxf(fmaxf(v0.x, v0.y), fmaxf(v0.z, v0.w)),
                     fmaxf(fmaxf(v1.x, v1.y), fmaxf(v1.z, v1.w)));
#pragma unroll
    for (int o = 16; o; o >>= 1) mx = fmaxf(mx, __shfl_xor_sync(0xffffffffu, mx, o));

    __shared__ float smax[8], ssum[8];
    if ((tid & 31) == 0) smax[tid >> 5] = mx;
    __syncthreads();
    float m = smax[0];
#pragma unroll
    for (int i = 1; i < 8; i++) m = fmaxf(m, smax[i]);

    v0.x = __expf(v0.x - m); v0.y = __expf(v0.y - m);
    v0.z = __expf(v0.z - m); v0.w = __expf(v0.w - m);
    v1.x = __expf(v1.x - m); v1.y = __expf(v1.y - m);
    v1.z = __expf(v1.z - m); v1.w = __expf(v1.w - m);

    float s = v0.x + v0.y + v0.z + v0.w + v1.x + v1.y + v1.z + v1.w;
#pragma unroll
    for (int o = 16; o; o >>= 1) s += __shfl_xor_sync(0xffffffffu, s, o);
    if ((tid & 31) == 0) ssum[tid >> 5] = s;
    __syncthreads();
    float tot = 0.0f;
#pragma unroll
    for (int i = 0; i < 8; i++) tot += ssum[i];
    const float inv = 1.0f / tot;

    v0.x *= inv; v0.y *= inv; v0.z *= inv; v0.w *= inv;
    v1.x *= inv; v1.y *= inv; v1.z *= inv; v1.w *= inv;
    p[tid] = v0;
    p[tid + 256] = v1;

    if (rr >= 1024) {
        const size_t base = (size_t)zz * 2097152 + (size_t)(rr - 1024) * 2048;
        float vals[8] = {v0.x, v0.y, v0.z, v0.w, v1.x, v1.y, v1.z, v1.w};
        const int cols[2] = {4 * tid, 1024 + 4 * tid};
#pragma unroll
        for (int half = 0; half < 2; ++half) {
            __nv_bfloat16 h[4], l[4];
#pragma unroll
            for (int j = 0; j < 4; ++j) {
                float vv = vals[half * 4 + j];
                h[j] = __float2bfloat16(vv);
                l[j] = __float2bfloat16(vv - __bfloat162float(h[j]));
            }
            size_t o = base + cols[half];
            *reinterpret_cast<__nv_bfloat162*>(&lhi[o])     = {h[0], h[1]};
            *reinterpret_cast<__nv_bfloat162*>(&lhi[o + 2]) = {h[2], h[3]};
            *reinterpret_cast<__nv_bfloat162*>(&llo[o])     = {l[0], l[1]};
            *reinterpret_cast<__nv_bfloat162*>(&llo[o + 2]) = {l[2], l[3]};
        }
    }
}

// ============================================================================
// Launch
// ============================================================================
extern "C" void kernel_launch(void* const* d_in, const int* in_sizes, int n_in,
                              void* d_out, int out_size)
{
    const float* x   = (const float*)d_in[0];
    const float* Wq  = (const float*)d_in[1];
    const float* bq  = (const float*)d_in[2];
    const float* Wk  = (const float*)d_in[3];
    const float* bk  = (const float*)d_in[4];
    const float* Wv  = (const float*)d_in[5];
    const float* bv  = (const float*)d_in[6];
    const float* Wo  = (const float*)d_in[7];
    const float* bo  = (const float*)d_in[8];
    const float* M1  = (const float*)d_in[9];
    const float* bm1 = (const float*)d_in[10];
    const float* M2  = (const float*)d_in[11];
    const float* bm2 = (const float*)d_in[12];

    float* out  = (float*)d_out;                      // (2,1024,1024)
    float* attn = out + (size_t)2 * 1024 * 1024;      // (2,16,2048,2048)

    __nv_bfloat16 *wHi, *wLo, *enhHi, *enhLo, *hHi, *hLo, *qHi, *qLo,
                  *kHi, *kLo, *vtHi, *vtLo, *alHi, *alLo, *cxHi, *cxLo;
    cudaGetSymbolAddress((void**)&wHi,  g_w_hi);
    cudaGetSymbolAddress((void**)&wLo,  g_w_lo);
    cudaGetSymbolAddress((void**)&enhHi, g_enh_hi);
    cudaGetSymbolAddress((void**)&enhLo, g_enh_lo);
    cudaGetSymbolAddress((void**)&hHi,  g_h_hi);
    cudaGetSymbolAddress((void**)&hLo,  g_h_lo);
    cudaGetSymbolAddress((void**)&qHi,  g_q_hi);
    cudaGetSymbolAddress((void**)&qLo,  g_q_lo);
    cudaGetSymbolAddress((void**)&kHi,  g_k_hi);
    cudaGetSymbolAddress((void**)&kLo,  g_k_lo);
    cudaGetSymbolAddress((void**)&vtHi, g_vt_hi);
    cudaGetSymbolAddress((void**)&vtLo, g_vt_lo);
    cudaGetSymbolAddress((void**)&alHi, g_al_hi);
    cudaGetSymbolAddress((void**)&alLo, g_al_lo);
    cudaGetSymbolAddress((void**)&cxHi, g_ctx_hi);
    cudaGetSymbolAddress((void**)&cxLo, g_ctx_lo);

    const size_t MW = 1048576;
    const int SMEM128 = (2 * 128 + 2 * 128) * 80 * 2;   // 81920
    const int SMEM64  = (2 * 128 + 2 * 64) * 80 * 2;    // 61440
    cudaFuncSetAttribute(gemm3_mma<128>, cudaFuncAttributeMaxDynamicSharedMemorySize, SMEM128);
    cudaFuncSetAttribute(gemm3_mma<64>,  cudaFuncAttributeMaxDynamicSharedMemorySize, SMEM64);

    // 0) convert weights + x into hi/lo bf16
    conv_kernel<<<1024, 256>>>(M1, wHi + 0 * MW, wLo + 0 * MW, 262144);
    conv_kernel<<<1024, 256>>>(M2, wHi + 1 * MW, wLo + 1 * MW, 262144);
    conv_kernel<<<1024, 256>>>(Wq, wHi + 2 * MW, wLo + 2 * MW, 262144);
    conv_kernel<<<1024, 256>>>(Wk, wHi + 3 * MW, wLo + 3 * MW, 262144);
    conv_kernel<<<1024, 256>>>(Wv, wHi + 4 * MW, wLo + 4 * MW, 262144);
    conv_kernel<<<1024, 256>>>(Wo, wHi + 5 * MW, wLo + 5 * MW, 262144);
    conv_kernel<<<2048, 256>>>(x, enhHi + 2097152, enhLo + 2097152, 524288);

    // 1) h = relu(x @ M1^T + bm1)
    gemm3_mma<128><<<dim3(8, 16), 256, SMEM128>>>(
        enhHi + 2097152, enhLo + 2097152, wHi + 0 * MW, wLo + 0 * MW, bm1,
        nullptr, hHi, hLo, 1024, 1024, 1024, 1024, 1.0f, 1, 0, 0);
    // 2) enh[0:2048] = h @ M2^T + bm2
    gemm3_mma<128><<<dim3(8, 16), 256, SMEM128>>>(
        hHi, hLo, wHi + 1 * MW, wLo + 1 * MW, bm2,
        nullptr, enhHi, enhLo, 1024, 1024, 1024, 1024, 1.0f, 0, 0, 0);
    // 3) Q, K, V(transposed) = enh @ W^T + b
    gemm3_mma<128><<<dim3(8, 32), 256, SMEM128>>>(
        enhHi, enhLo, wHi + 2 * MW, wLo + 2 * MW, bq,
        nullptr, qHi, qLo, 1024, 1024, 1024, 1024, 1.0f, 0, 0, 0);
    gemm3_mma<128><<<dim3(8, 32), 256, SMEM128>>>(
        enhHi, enhLo, wHi + 3 * MW, wLo + 3 * MW, bk,
        nullptr, kHi, kLo, 1024, 1024, 1024, 1024, 1.0f, 0, 0, 0);
    gemm3_mma<128><<<dim3(8, 32), 256, SMEM128>>>(
        enhHi, enhLo, wHi + 4 * MW, wLo + 4 * MW, bv,
        nullptr, vtHi, vtLo, 1024, 1024, 1024, 1024, 1.0f, 0, 0, 1);
    // 4) attn_raw = 0.125 * Q_bh @ K_bh^T  (fp32 -> attn region)
    gemm3_mma<128><<<dim3(16, 16, 32), 256, SMEM128>>>(
        qHi, qLo, kHi, kLo, nullptr,
        attn, nullptr, nullptr, 64, 1024, 1024, 2048, 0.125f, 0, 1, 0);
    // 5) softmax in-place + export lower-half hi/lo
    softmax_kernel<<<65536, 256>>>(attn, alHi, alLo);
    // 6) ctx = attn[., 1024:, :] @ V_bh   (BN=64, K=2048)
    gemm3_mma<64><<<dim3(1, 8, 32), 256, SMEM64>>>(
        alHi, alLo, vtHi, vtLo, nullptr,
        nullptr, cxHi, cxLo, 2048, 2048, 2048, 1024, 1.0f, 0, 2, 0);
    // 7) out = ctx @ Wo^T + bo  (fp32)
    gemm3_mma<128><<<dim3(8, 16), 256, SMEM128>>>(
        cxHi, cxLo, wHi + 5 * MW, wLo + 5 * MW, bo,
        out, nullptr, nullptr, 1024, 1024, 1024, 1024, 1.0f, 0, 0, 0);
}

// round 6
// speedup vs baseline: 2.3954x; 1.0432x over previous
#include <cuda_runtime.h>
#include <cuda_bf16.h>
#include <cstdint>
#include <cstddef>

// ============================================================================
// helpers (base sm_103 ISA only: ldmatrix + mma.sync + cp.async)
// ============================================================================
__device__ __forceinline__ uint32_t smem_u32(const void* p) {
    uint32_t a;
    asm("{ .reg .u64 t; cvta.to.shared.u64 t, %1; cvt.u32.u64 %0, t; }"
        : "=r"(a) : "l"(p));
    return a;
}

#define CP16(dst, src) \
    asm volatile("cp.async.cg.shared.global [%0], [%1], 16;" \
                 :: "r"(dst), "l"(src) : "memory")
#define CP_COMMIT() asm volatile("cp.async.commit_group;" ::: "memory")
#define CP_WAIT1()  asm volatile("cp.async.wait_group 1;" ::: "memory")
#define CP_WAIT0()  asm volatile("cp.async.wait_group 0;" ::: "memory")

#define LDSM4(r, addr) \
    asm volatile("ldmatrix.sync.aligned.m8n8.x4.shared.b16 {%0,%1,%2,%3}, [%4];" \
                 : "=r"((r)[0]), "=r"((r)[1]), "=r"((r)[2]), "=r"((r)[3]) : "r"(addr))

#define MMA16816(d, a, b0, b1) \
    asm volatile("mma.sync.aligned.m16n8k16.row.col.f32.bf16.bf16.f32 " \
                 "{%0,%1,%2,%3},{%4,%5,%6,%7},{%8,%9},{%0,%1,%2,%3};" \
                 : "+f"((d)[0]), "+f"((d)[1]), "+f"((d)[2]), "+f"((d)[3]) \
                 : "r"((a)[0]), "r"((a)[1]), "r"((a)[2]), "r"((a)[3]), \
                   "r"(b0), "r"(b1))

#define STS128U(addr, r) \
    asm volatile("st.shared.v4.b32 [%0], {%1, %2, %3, %4};" \
                 :: "r"(addr), "r"((r)[0]), "r"((r)[1]), "r"((r)[2]), "r"((r)[3]) : "memory")

__device__ __forceinline__ uint32_t packbf2(float f0, float f1) {
    __nv_bfloat162 t(__float2bfloat16(f0), __float2bfloat16(f1));
    return *reinterpret_cast<uint32_t*>(&t);
}

// ============================================================================
// Scratch (device globals; no allocations allowed)
// ============================================================================
__device__ __align__(16) __nv_bfloat16 g_w_hi[6 * 1048576];   // [M1,M2,Wq,Wk,Wv,Wo]
__device__ __align__(16) __nv_bfloat16 g_w_lo[6 * 1048576];
__device__ __align__(16) __nv_bfloat16 g_enh_hi[4194304], g_enh_lo[4194304]; // [mem;x]
__device__ __align__(16) __nv_bfloat16 g_h_hi[2097152],  g_h_lo[2097152];
__device__ __align__(16) __nv_bfloat16 g_q_hi[4194304],  g_q_lo[4194304];
__device__ __align__(16) __nv_bfloat16 g_k_hi[4194304],  g_k_lo[4194304];
__device__ __align__(16) __nv_bfloat16 g_vt_hi[4194304], g_vt_lo[4194304];   // [32][64][2048]
__device__ __align__(16) __nv_bfloat16 g_ctx_hi[2097152], g_ctx_lo[2097152];
__device__ __align__(16) float g_sc[16777216];   // 67 MB: raw scores for 4 heads (L2-hot)

// ============================================================================
// fp32 -> (bf16 hi, bf16 lo) conversions
// ============================================================================
__global__ void __launch_bounds__(256) conv_w_kernel(
    const float* __restrict__ s0, const float* __restrict__ s1,
    const float* __restrict__ s2, const float* __restrict__ s3,
    const float* __restrict__ s4, const float* __restrict__ s5,
    __nv_bfloat16* __restrict__ hi, __nv_bfloat16* __restrict__ lo)
{
    const int w = blockIdx.y;
    const float* src = (w == 0) ? s0 : (w == 1) ? s1 : (w == 2) ? s2
                    : (w == 3) ? s3 : (w == 4) ? s4 : s5;
    hi += (size_t)w * 1048576;
    lo += (size_t)w * 1048576;
    int i = blockIdx.x * 256 + threadIdx.x;           // n4 = 262144
    float4 v = reinterpret_cast<const float4*>(src)[i];
    float vals[4] = {v.x, v.y, v.z, v.w};
    __nv_bfloat16 h[4], l[4];
#pragma unroll
    for (int j = 0; j < 4; ++j) {
        h[j] = __float2bfloat16(vals[j]);
        l[j] = __float2bfloat16(vals[j] - __bfloat162float(h[j]));
    }
    reinterpret_cast<__nv_bfloat162*>(hi)[2 * i]     = {h[0], h[1]};
    reinterpret_cast<__nv_bfloat162*>(hi)[2 * i + 1] = {h[2], h[3]};
    reinterpret_cast<__nv_bfloat162*>(lo)[2 * i]     = {l[0], l[1]};
    reinterpret_cast<__nv_bfloat162*>(lo)[2 * i + 1] = {l[2], l[3]};
}

__global__ void __launch_bounds__(256) conv_kernel(
    const float* __restrict__ src, __nv_bfloat16* __restrict__ hi,
    __nv_bfloat16* __restrict__ lo, int n4)
{
    int i = blockIdx.x * 256 + threadIdx.x;
    if (i >= n4) return;
    float4 v = reinterpret_cast<const float4*>(src)[i];
    float vals[4] = {v.x, v.y, v.z, v.w};
    __nv_bfloat16 h[4], l[4];
#pragma unroll
    for (int j = 0; j < 4; ++j) {
        h[j] = __float2bfloat16(vals[j]);
        l[j] = __float2bfloat16(vals[j] - __bfloat162float(h[j]));
    }
    reinterpret_cast<__nv_bfloat162*>(hi)[2 * i]     = {h[0], h[1]};
    reinterpret_cast<__nv_bfloat162*>(hi)[2 * i + 1] = {h[2], h[3]};
    reinterpret_cast<__nv_bfloat162*>(lo)[2 * i]     = {l[0], l[1]};
    reinterpret_cast<__nv_bfloat162*>(lo)[2 * i + 1] = {l[2], l[3]};
}

// ============================================================================
// bf16x3 NT GEMM via mma.sync: C = act(scale*(A@B^T) + bias)
// 3 fused passes per K-chunk: Ahi*Bhi + Alo*Bhi + Ahi*Blo, fp32 reg accum.
// MODE 0: plain    (z unused)
// MODE 1: QK       A,B offset by global z=zbase+bz; C = scratch at local z
// MODE 2: AV       A read from fp32 attn (lower half, __ldcs) + in-kernel split
// transV: scatter C into Vt[32][64][2048]
// ============================================================================
template <int BN, int MODE>
__global__ void __launch_bounds__(256, 2) gemm3_mma(
    const __nv_bfloat16* __restrict__ Ahi, const __nv_bfloat16* __restrict__ Alo,
    const float* __restrict__ Af,
    const __nv_bfloat16* __restrict__ Bhi, const __nv_bfloat16* __restrict__ Blo,
    const float* __restrict__ bias,
    float* __restrict__ Cf, __nv_bfloat16* __restrict__ Chi, __nv_bfloat16* __restrict__ Clo,
    int K, int lda, int ldb, int ldc,
    float scale, int relu, int zbase, int transV)
{
    extern __shared__ __align__(128) char smem[];
    constexpr int STRIDE = 80;                 // 64B row + 16B pad
    constexpr int A_BYTES = 128 * STRIDE;
    constexpr int B_BYTES = BN * STRIDE;
    constexpr int STAGE = 2 * A_BYTES + 2 * B_BYTES;
    constexpr int WM = (BN == 128) ? 2 : 1;

    const int tid = threadIdx.x;
    const int wid = tid >> 5, lid = tid & 31;
    const int m0 = blockIdx.y * 128;
    const int n0 = blockIdx.x * BN;
    const int z  = (MODE == 1) ? (zbase + blockIdx.z) : blockIdx.z;

    const int r0 = (BN == 128) ? ((wid >> 1) * 32) : (wid * 16);
    const int c0 = (BN == 128) ? ((wid & 1) * 64) : 0;

    size_t aOff = 0, bOff = 0;
    if (MODE == 1) {
        aOff = bOff = (size_t)(z >> 4) * 2097152 + (size_t)(z & 15) * 64;
    } else if (MODE == 2) {
        bOff = (size_t)z * 131072;
    }
    if (MODE != 2) { Ahi += aOff; Alo += aOff; }
    Bhi += bOff; Blo += bOff;

    const uint32_t sbase = smem_u32(smem);

    auto issueA = [&](int c) {
        const int kt = c << 5;
        const uint32_t sb = sbase + (c & 1) * STAGE;
#pragma unroll
        for (int u = 0; u < 2; ++u) {
            int id = tid + u * 256;
            int row = id >> 2, seg = id & 3;
            const char* sH = (const char*)(Ahi + (size_t)(m0 + row) * lda + kt) + seg * 16;
            const char* sL = (const char*)(Alo + (size_t)(m0 + row) * lda + kt) + seg * 16;
            uint32_t d = sb + row * STRIDE + seg * 16;
            CP16(d, sH);
            CP16(d + A_BYTES, sL);
        }
    };
    auto issueB = [&](int c) {
        const int kt = c << 5;
        const uint32_t sb = sbase + (c & 1) * STAGE;
        constexpr int BU = (BN * 4) / 256;
#pragma unroll
        for (int u = 0; u < BU; ++u) {
            int id = tid + u * 256;
            int row = id >> 2, seg = id & 3;
            const char* sH = (const char*)(Bhi + (size_t)(n0 + row) * ldb + kt) + seg * 16;
            const char* sL = (const char*)(Blo + (size_t)(n0 + row) * ldb + kt) + seg * 16;
            uint32_t d = sb + 2 * A_BYTES + row * STRIDE + seg * 16;
            CP16(d, sH);
            CP16(d + B_BYTES, sL);
        }
    };

    float acc[WM][8][4];
#pragma unroll
    for (int i = 0; i < WM; ++i)
#pragma unroll
        for (int j = 0; j < 8; ++j)
#pragma unroll
            for (int q = 0; q < 4; ++q) acc[i][j][q] = 0.0f;

    // per-warp ldmatrix address components
    const uint32_t aRow = (uint32_t)(r0 + (lid & 15)) * STRIDE + ((lid >> 4) & 1) * 16;
    const uint32_t bRow = (uint32_t)(c0 + (lid & 7) + ((lid >> 4) & 1) * 8) * STRIDE
                        + ((lid >> 3) & 1) * 16;

    auto mma_chunk = [&](int c) {
        const uint32_t sb = sbase + (c & 1) * STAGE;
        const uint32_t aH = sb, aL = sb + A_BYTES;
        const uint32_t bH = sb + 2 * A_BYTES, bL = bH + B_BYTES;
#pragma unroll
        for (int s = 0; s < 2; ++s) {
            uint32_t ah[WM][4], al[WM][4], bb[4][4];
#pragma unroll
            for (int i = 0; i < WM; ++i) {
                LDSM4(ah[i], aH + aRow + i * 16 * STRIDE + s * 32);
                LDSM4(al[i], aL + aRow + i * 16 * STRIDE + s * 32);
            }
#pragma unroll
            for (int j = 0; j < 4; ++j)
                LDSM4(bb[j], bH + bRow + j * 16 * STRIDE + s * 32);
#pragma unroll
            for (int i = 0; i < WM; ++i)
#pragma unroll
                for (int jt = 0; jt < 8; ++jt) {
                    MMA16816(acc[i][jt], ah[i], bb[jt >> 1][(jt & 1) * 2], bb[jt >> 1][(jt & 1) * 2 + 1]);
                    MMA16816(acc[i][jt], al[i], bb[jt >> 1][(jt & 1) * 2], bb[jt >> 1][(jt & 1) * 2 + 1]);
                }
#pragma unroll
            for (int j = 0; j < 4; ++j)
                LDSM4(bb[j], bL + bRow + j * 16 * STRIDE + s * 32);
#pragma unroll
            for (int i = 0; i < WM; ++i)
#pragma unroll
                for (int jt = 0; jt < 8; ++jt)
                    MMA16816(acc[i][jt], ah[i], bb[jt >> 1][(jt & 1) * 2], bb[jt >> 1][(jt & 1) * 2 + 1]);
        }
    };

    const int nC = K >> 5;

    if constexpr (MODE != 2) {
        issueA(0); issueB(0); CP_COMMIT();
        for (int c = 0; c < nC; ++c) {
            if (c + 1 < nC) { issueA(c + 1); issueB(c + 1); CP_COMMIT(); CP_WAIT1(); }
            else            { CP_WAIT0(); }
            __syncthreads();
            mma_chunk(c);
            __syncthreads();
        }
    } else {
        // A comes from fp32 attn (lower half): reg-staged load + convert + STS
        const float* Abase = Af + (size_t)z * 4194304 + (size_t)1024 * 2048;
        const int arow = tid >> 1, acol = (tid & 1) * 16;
        const float* Aptr = Abase + (size_t)(m0 + arow) * 2048 + acol;

        auto ldA = [&](int c, float4* r) {
            const float4* p = reinterpret_cast<const float4*>(Aptr + (c << 5));
#pragma unroll
            for (int j = 0; j < 4; ++j) r[j] = __ldcs(p + j);
        };
        auto stsA = [&](int c, const float4* r) {
            const uint32_t sb = sbase + (c & 1) * STAGE;
            const uint32_t d = sb + arow * STRIDE + acol * 2;
#pragma unroll
            for (int half = 0; half < 2; ++half) {
                float f[4] = {r[2 * half].x, r[2 * half].y, r[2 * half].z, r[2 * half].w};
                float g4[4] = {r[2 * half + 1].x, r[2 * half + 1].y,
                               r[2 * half + 1].z, r[2 * half + 1].w};
                uint32_t hp[4], lp[4];
#pragma unroll
                for (int q = 0; q < 2; ++q) {
                    float f0 = f[2 * q], f1 = f[2 * q + 1];
                    __nv_bfloat16 h0 = __float2bfloat16(f0), h1 = __float2bfloat16(f1);
                    hp[q] = packbf2(f0, f1);
                    lp[q] = packbf2(f0 - __bfloat162float(h0), f1 - __bfloat162float(h1));
                }
#pragma unroll
                for (int q = 0; q < 2; ++q) {
                    float f0 = g4[2 * q], f1 = g4[2 * q + 1];
                    __nv_bfloat16 h0 = __float2bfloat16(f0), h1 = __float2bfloat16(f1);
                    hp[2 + q] = packbf2(f0, f1);
                    lp[2 + q] = packbf2(f0 - __bfloat162float(h0), f1 - __bfloat162float(h1));
                }
                STS128U(d + half * 16, hp);
                STS128U(d + half * 16 + A_BYTES, lp);
            }
        };

        float4 cur[4], nxt[4];
        ldA(0, cur);
        issueB(0); CP_COMMIT();
        for (int c = 0; c < nC; ++c) {
            stsA(c, cur);
            if (c + 1 < nC) { ldA(c + 1, nxt); issueB(c + 1); CP_COMMIT(); CP_WAIT1(); }
            else            { CP_WAIT0(); }
            __syncthreads();
            mma_chunk(c);
            __syncthreads();
#pragma unroll
            for (int j = 0; j < 4; ++j) cur[j] = nxt[j];
        }
    }

    // ---------------- epilogue ----------------
    size_t cOffZ = 0;
    if constexpr (MODE == 1)      cOffZ = (size_t)blockIdx.z * 4194304;     // local z in scratch
    else if constexpr (MODE == 2) cOffZ = (size_t)(z >> 4) * 1048576 + (size_t)(z & 15) * 64;

    const int grp = lid >> 2, tig = lid & 3;

#pragma unroll
    for (int i = 0; i < WM; ++i) {
#pragma unroll
        for (int jt = 0; jt < 8; ++jt) {
            const int mr = m0 + r0 + i * 16 + grp;
            const int nc = n0 + c0 + jt * 8 + tig * 2;
            float v0 = acc[i][jt][0] * scale, v1 = acc[i][jt][1] * scale;
            float v2 = acc[i][jt][2] * scale, v3 = acc[i][jt][3] * scale;
            if (bias) {
                float b0 = __ldg(bias + nc), b1 = __ldg(bias + nc + 1);
                v0 += b0; v1 += b1; v2 += b0; v3 += b1;
            }
            if (relu) {
                v0 = fmaxf(v0, 0.0f); v1 = fmaxf(v1, 0.0f);
                v2 = fmaxf(v2, 0.0f); v3 = fmaxf(v3, 0.0f);
            }
            if (Cf) {
                *reinterpret_cast<float2*>(&Cf[cOffZ + (size_t)mr * ldc + nc]) =
                    make_float2(v0, v1);
                *reinterpret_cast<float2*>(&Cf[cOffZ + (size_t)(mr + 8) * ldc + nc]) =
                    make_float2(v2, v3);
            }
            if (Chi) {
                __nv_bfloat16 h0 = __float2bfloat16(v0), h1 = __float2bfloat16(v1);
                __nv_bfloat16 h2 = __float2bfloat16(v2), h3 = __float2bfloat16(v3);
                __nv_bfloat16 l0 = __float2bfloat16(v0 - __bfloat162float(h0));
                __nv_bfloat16 l1 = __float2bfloat16(v1 - __bfloat162float(h1));
                __nv_bfloat16 l2 = __float2bfloat16(v2 - __bfloat162float(h2));
                __nv_bfloat16 l3 = __float2bfloat16(v3 - __bfloat162float(h3));
                if (!transV) {
                    size_t i0 = cOffZ + (size_t)mr * ldc + nc;
                    size_t i1 = cOffZ + (size_t)(mr + 8) * ldc + nc;
                    *reinterpret_cast<__nv_bfloat162*>(&Chi[i0]) = {h0, h1};
                    *reinterpret_cast<__nv_bfloat162*>(&Chi[i1]) = {h2, h3};
                    *reinterpret_cast<__nv_bfloat162*>(&Clo[i0]) = {l0, l1};
                    *reinterpret_cast<__nv_bfloat162*>(&Clo[i1]) = {l2, l3};
                } else {
#pragma unroll
                    for (int e = 0; e < 4; ++e) {
                        int rr = mr + (e >> 1) * 8;
                        int nn = nc + (e & 1);
                        size_t idx = ((size_t)(rr >> 11) * 16 + (size_t)(nn >> 6)) * 131072
                                   + (size_t)(nn & 63) * 2048 + (size_t)(rr & 2047);
                        __nv_bfloat16 hv = (e == 0) ? h0 : (e == 1) ? h1 : (e == 2) ? h2 : h3;
                        __nv_bfloat16 lv = (e == 0) ? l0 : (e == 1) ? l1 : (e == 2) ? l2 : l3;
                        Chi[idx] = hv;
                        Clo[idx] = lv;
                    }
                }
            }
        }
    }
}

// ============================================================================
// Row softmax: scratch (L2-hot, 4 heads) -> attn output (streaming .cs)
// ============================================================================
__global__ void __launch_bounds__(256) softmax_kernel(
    const float* __restrict__ scratch, float* __restrict__ attn, int zbase)
{
    const int zloc = blockIdx.x >> 11;
    const int rr = blockIdx.x & 2047;
    const float4* p = reinterpret_cast<const float4*>(
        scratch + (size_t)zloc * 4194304 + (size_t)rr * 2048);
    float4* q = reinterpret_cast<float4*>(
        attn + (size_t)(zbase + zloc) * 4194304 + (size_t)rr * 2048);
    const int tid = threadIdx.x;
    float4 v0 = p[tid];
    float4 v1 = p[tid + 256];

    float mx = fmaxf(fmaxf(fmaxf(v0.x, v0.y), fmaxf(v0.z, v0.w)),
                     fmaxf(fmaxf(v1.x, v1.y), fmaxf(v1.z, v1.w)));
#pragma unroll
    for (int o = 16; o; o >>= 1) mx = fmaxf(mx, __shfl_xor_sync(0xffffffffu, mx, o));

    __shared__ float smax[8], ssum[8];
    if ((tid & 31) == 0) smax[tid >> 5] = mx;
    __syncthreads();
    float m = smax[0];
#pragma unroll
    for (int i = 1; i < 8; i++) m = fmaxf(m, smax[i]);

    v0.x = __expf(v0.x - m); v0.y = __expf(v0.y - m);
    v0.z = __expf(v0.z - m); v0.w = __expf(v0.w - m);
    v1.x = __expf(v1.x - m); v1.y = __expf(v1.y - m);
    v1.z = __expf(v1.z - m); v1.w = __expf(v1.w - m);

    float s = v0.x + v0.y + v0.z + v0.w + v1.x + v1.y + v1.z + v1.w;
#pragma unroll
    for (int o = 16; o; o >>= 1) s += __shfl_xor_sync(0xffffffffu, s, o);
    if ((tid & 31) == 0) ssum[tid >> 5] = s;
    __syncthreads();
    float tot = 0.0f;
#pragma unroll
    for (int i = 0; i < 8; i++) tot += ssum[i];
    const float inv = 1.0f / tot;

    v0.x *= inv; v0.y *= inv; v0.z *= inv; v0.w *= inv;
    v1.x *= inv; v1.y *= inv; v1.z *= inv; v1.w *= inv;
    __stcs(q + tid, v0);
    __stcs(q + tid + 256, v1);
}

// ============================================================================
// Launch
// ============================================================================
extern "C" void kernel_launch(void* const* d_in, const int* in_sizes, int n_in,
                              void* d_out, int out_size)
{
    const float* x   = (const float*)d_in[0];
    const float* Wq  = (const float*)d_in[1];
    const float* bq  = (const float*)d_in[2];
    const float* Wk  = (const float*)d_in[3];
    const float* bk  = (const float*)d_in[4];
    const float* Wv  = (const float*)d_in[5];
    const float* bv  = (const float*)d_in[6];
    const float* Wo  = (const float*)d_in[7];
    const float* bo  = (const float*)d_in[8];
    const float* M1  = (const float*)d_in[9];
    const float* bm1 = (const float*)d_in[10];
    const float* M2  = (const float*)d_in[11];
    const float* bm2 = (const float*)d_in[12];

    float* out  = (float*)d_out;                      // (2,1024,1024)
    float* attn = out + (size_t)2 * 1024 * 1024;      // (2,16,2048,2048)

    __nv_bfloat16 *wHi, *wLo, *enhHi, *enhLo, *hHi, *hLo, *qHi, *qLo,
                  *kHi, *kLo, *vtHi, *vtLo, *cxHi, *cxLo;
    float* sc;
    cudaGetSymbolAddress((void**)&wHi,  g_w_hi);
    cudaGetSymbolAddress((void**)&wLo,  g_w_lo);
    cudaGetSymbolAddress((void**)&enhHi, g_enh_hi);
    cudaGetSymbolAddress((void**)&enhLo, g_enh_lo);
    cudaGetSymbolAddress((void**)&hHi,  g_h_hi);
    cudaGetSymbolAddress((void**)&hLo,  g_h_lo);
    cudaGetSymbolAddress((void**)&qHi,  g_q_hi);
    cudaGetSymbolAddress((void**)&qLo,  g_q_lo);
    cudaGetSymbolAddress((void**)&kHi,  g_k_hi);
    cudaGetSymbolAddress((void**)&kLo,  g_k_lo);
    cudaGetSymbolAddress((void**)&vtHi, g_vt_hi);
    cudaGetSymbolAddress((void**)&vtLo, g_vt_lo);
    cudaGetSymbolAddress((void**)&cxHi, g_ctx_hi);
    cudaGetSymbolAddress((void**)&cxLo, g_ctx_lo);
    cudaGetSymbolAddress((void**)&sc,   g_sc);

    const size_t MW = 1048576;
    const int SMEM128 = (2 * 128 + 2 * 128) * 80 * 2;   // 81920
    const int SMEM64  = (2 * 128 + 2 * 64) * 80 * 2;    // 61440
    cudaFuncSetAttribute(gemm3_mma<128, 0>, cudaFuncAttributeMaxDynamicSharedMemorySize, SMEM128);
    cudaFuncSetAttribute(gemm3_mma<128, 1>, cudaFuncAttributeMaxDynamicSharedMemorySize, SMEM128);
    cudaFuncSetAttribute(gemm3_mma<64, 2>,  cudaFuncAttributeMaxDynamicSharedMemorySize, SMEM64);

    // 0) convert weights + x into hi/lo bf16  (2 launches)
    conv_w_kernel<<<dim3(1024, 6), 256>>>(M1, M2, Wq, Wk, Wv, Wo, wHi, wLo);
    conv_kernel<<<2048, 256>>>(x, enhHi + 2097152, enhLo + 2097152, 524288);

    // 1) h = relu(x @ M1^T + bm1)
    gemm3_mma<128, 0><<<dim3(8, 16), 256, SMEM128>>>(
        enhHi + 2097152, enhLo + 2097152, nullptr, wHi + 0 * MW, wLo + 0 * MW, bm1,
        nullptr, hHi, hLo, 1024, 1024, 1024, 1024, 1.0f, 1, 0, 0);
    // 2) enh[0:2048] = h @ M2^T + bm2
    gemm3_mma<128, 0><<<dim3(8, 16), 256, SMEM128>>>(
        hHi, hLo, nullptr, wHi + 1 * MW, wLo + 1 * MW, bm2,
        nullptr, enhHi, enhLo, 1024, 1024, 1024, 1024, 1.0f, 0, 0, 0);
    // 3) Q, K, V(transposed) = enh @ W^T + b
    gemm3_mma<128, 0><<<dim3(8, 32), 256, SMEM128>>>(
        enhHi, enhLo, nullptr, wHi + 2 * MW, wLo + 2 * MW, bq,
        nullptr, qHi, qLo, 1024, 1024, 1024, 1024, 1.0f, 0, 0, 0);
    gemm3_mma<128, 0><<<dim3(8, 32), 256, SMEM128>>>(
        enhHi, enhLo, nullptr, wHi + 3 * MW, wLo + 3 * MW, bk,
        nullptr, kHi, kLo, 1024, 1024, 1024, 1024, 1.0f, 0, 0, 0);
    gemm3_mma<128, 0><<<dim3(8, 32), 256, SMEM128>>>(
        enhHi, enhLo, nullptr, wHi + 4 * MW, wLo + 4 * MW, bv,
        nullptr, vtHi, vtLo, 1024, 1024, 1024, 1024, 1.0f, 0, 0, 1);

    // 4+5) per 4-head group: QK scores -> L2-hot scratch, softmax -> attn
    for (int g = 0; g < 8; ++g) {
        gemm3_mma<128, 1><<<dim3(16, 16, 4), 256, SMEM128>>>(
            qHi, qLo, nullptr, kHi, kLo, nullptr,
            sc, nullptr, nullptr, 64, 1024, 1024, 2048, 0.125f, 0, g * 4, 0);
        softmax_kernel<<<8192, 256>>>(sc, attn, g * 4);
    }

    // 6) ctx = attn[., 1024:, :] @ V_bh  (A = fp32 attn, split in-kernel)
    gemm3_mma<64, 2><<<dim3(1, 8, 32), 256, SMEM64>>>(
        nullptr, nullptr, attn, vtHi, vtLo, nullptr,
        nullptr, cxHi, cxLo, 2048, 2048, 2048, 1024, 1.0f, 0, 0, 0);
    // 7) out = ctx @ Wo^T + bo  (fp32)
    gemm3_mma<128, 0><<<dim3(8, 16), 256, SMEM128>>>(
        cxHi, cxLo, nullptr, wHi + 5 * MW, wLo + 5 * MW, bo,
        out, nullptr, nullptr, 1024, 1024, 1024, 1024, 1.0f, 0, 0, 0);
}